// round 9
// baseline (speedup 1.0000x reference)
#include <cuda_runtime.h>
#include <cstdint>

// LSTM_1279900254644: 2-layer LSTM, B=512, L=1000, H=128.
// Cluster-of-4, weights SMEM-resident. This round: warp-tiled (R4 x M4) gate
// matmuls with phase-distinct LDS (zero-waste weight wavefronts), h resident
// in registers per warp, bias/x folded into cell stage.

#define B_DIM 512
#define L_DIM 1000
#define H_DIM 128
#define MB    16
#define NCL   32
#define NBLK  (NCL * 4)
#define BLK_T 512
#define WSTRIDE 129         // ull2 slots per k4-row; 129*4 % 32 == 4 -> conflict-free
#define W_BYTES (96 * WSTRIDE * 16)   // 198144
#define GSTRIDE 18          // gsm floats per row (2-way max conflict on cell reads)
#define SMEM_BYTES (W_BYTES + (2*MB*128 + MB*128 + 128*GSTRIDE + 2*MB + 4*MB) * 4)

// Packed weights, per-CTA order: [rank 4][mat 3][k4 32][row 128] as 16B chunks.
__device__ ulonglong2 g_wpack[4 * 96 * 128];

typedef unsigned long long ull;

__device__ __forceinline__ void ffma2(ull& d, ull a, ull b) {
    asm("fma.rn.f32x2 %0, %1, %2, %0;" : "+l"(d) : "l"(a), "l"(b));
}
__device__ __forceinline__ float pksum(ull v) {
    float a, b;
    asm("mov.b64 {%0,%1}, %2;" : "=f"(a), "=f"(b) : "l"(v));
    return a + b;
}
__device__ __forceinline__ float sigf(float x) {
    return __fdividef(1.f, 1.f + __expf(-x));
}
__device__ __forceinline__ float tanh_fast(float x) {
    return 1.f - __fdividef(2.f, __expf(2.f * x) + 1.f);
}
__device__ __forceinline__ uint32_t smem_u32(const void* p) {
    uint32_t a;
    asm("{ .reg .u64 t; cvta.to.shared.u64 t, %1; cvt.u32.u64 %0, t; }" : "=r"(a) : "l"(p));
    return a;
}
__device__ __forceinline__ void cluster_sync() {
    asm volatile("barrier.cluster.arrive.aligned;" ::: "memory");
    asm volatile("barrier.cluster.wait.aligned;" ::: "memory");
}
__device__ __forceinline__ void push_all(uint32_t laddr, float v) {
    #pragma unroll
    for (int r = 0; r < 4; ++r) {
        uint32_t ra;
        asm volatile("mapa.shared::cluster.u32 %0, %1, %2;" : "=r"(ra) : "r"(laddr), "r"(r));
        asm volatile("st.shared::cluster.f32 [%0], %1;" :: "r"(ra), "f"(v) : "memory");
    }
}
__device__ __forceinline__ void push_rank0(uint32_t laddr, float v) {
    uint32_t ra;
    asm volatile("mapa.shared::cluster.u32 %0, %1, %2;" : "=r"(ra) : "r"(laddr), "r"(0));
    asm volatile("st.shared::cluster.f32 [%0], %1;" :: "r"(ra), "f"(v) : "memory");
}

__global__ void pack_weights(const float* __restrict__ w1,
                             const float* __restrict__ w2i,
                             const float* __restrict__ w2h) {
    int idx = blockIdx.x * blockDim.x + threadIdx.x;   // [rank][mk][row]
    if (idx >= 4 * 96 * 128) return;
    int rl   = idx & 127;
    int mk   = (idx >> 7) % 96;
    int rank = idx / (96 * 128);
    int mat = mk / 32, k4 = mk % 32;
    int row = ((rl >> 5) << 7) + (rank << 5) + (rl & 31);   // 128*gate + 32*rank + dim
    const float* src = (mat == 0) ? w1 : (mat == 1) ? w2i : w2h;
    const float* s = src + row * H_DIM + 4 * k4;
    ull lo = ((ull)__float_as_uint(s[1]) << 32) | __float_as_uint(s[0]);
    ull hi = ((ull)__float_as_uint(s[3]) << 32) | __float_as_uint(s[2]);
    ulonglong2 v; v.x = lo; v.y = hi;
    g_wpack[idx] = v;
}

__global__ __launch_bounds__(BLK_T, 1) __cluster_dims__(4, 1, 1)
void lstm_main(const float* __restrict__ y,
               const float* __restrict__ Wih1,
               const float* __restrict__ bih1,
               const float* __restrict__ bhh1,
               const float* __restrict__ bih2,
               const float* __restrict__ bhh2,
               const float* __restrict__ Wlin,
               const float* __restrict__ blin,
               float* __restrict__ out) {
    extern __shared__ unsigned char smem_raw[];
    const int tid = threadIdx.x;
    uint32_t rank;
    asm("mov.u32 %0, %%cluster_ctarank;" : "=r"(rank));
    const int cl    = blockIdx.x >> 2;
    const int bbase = cl * MB;

    // ---- SMEM layout ----
    ulonglong2* Wsm = (ulonglong2*)smem_raw;                 // [96][129] 16B units
    float* h1s = (float*)(smem_raw + W_BYTES);               // [2][MB][128]
    float* h2s = h1s + 2 * MB * 128;                         // [MB][128]
    float* gsm = h2s + MB * 128;                             // [128][GSTRIDE]
    float* xs  = gsm + 128 * GSTRIDE;                        // [2][MB]
    float* outp = xs + 2 * MB;                               // [4][MB]

    const uint32_t h1_u32 = smem_u32(h1s);
    const uint32_t h2_u32 = smem_u32(h2s);
    const uint32_t op_u32 = smem_u32(outp);

    // ---- roles ----
    const int wid  = tid >> 5, lane = tid & 31;
    const int rg   = wid >> 2;            // row-group: rows rg*32 .. rg*32+31
    const int mg   = wid & 3;             // m-group:   m = mg*4 .. mg*4+3
    const int kq   = lane & 15;           // K-slice: k4 in {kq, kq+16}
    const int rp   = lane >> 4;           // row parity within row-pair
    const int m_c  = tid >> 5;            // cell role: batch 0..15
    const int d_c  = tid & 31;            // cell role: local dim

    // cell-stage constants (per-thread: 4 gate rows of dim d_c)
    float wih1r[4], b1r[4], b2r[4];
    #pragma unroll
    for (int g = 0; g < 4; ++g) {
        int grow = (g << 7) + ((int)rank << 5) + d_c;
        wih1r[g] = Wih1[grow];
        b1r[g]   = bih1[grow] + bhh1[grow];
        b2r[g]   = bih2[grow] + bhh2[grow];
    }
    const float wlin_d = Wlin[((int)rank << 5) + d_c];
    const float blin0  = blin[0];

    // ---- init ----
    for (int i = tid; i < 3 * MB * 128; i += BLK_T) h1s[i] = 0.f;   // h1(2 bufs)+h2
    for (int i = tid; i < 96 * 128; i += BLK_T) {
        int mk = i >> 7, r = i & 127;
        Wsm[mk * WSTRIDE + r] = g_wpack[(int)rank * 96 * 128 + i];
    }
    if (tid < MB) {
        int b = bbase + tid;
        xs[tid] = (b < B_DIM) ? y[b * L_DIM] : 0.f;
    }
    __syncthreads();
    cluster_sync();

    float c1 = 0.f, c2 = 0.f, h2n = 0.f;
    int p = 0;

    for (int t = 0; t < L_DIM; ++t) {
        // ---- phase 0: publish h2 (prev step's; zeros at t=0) ----
        push_all(h2_u32 + (((m_c << 7) + ((int)rank << 5) + d_c) << 2), h2n);

        // ---- stage A: layer-1 gates over h1[p] ----
        {
            const ulonglong2* hb = (const ulonglong2*)(h1s + p * MB * 128);
            ulonglong2 ha[4][2];
            #pragma unroll
            for (int m = 0; m < 4; ++m)
                #pragma unroll
                for (int jj = 0; jj < 2; ++jj)
                    ha[m][jj] = hb[((mg << 2) + m) * 32 + (jj << 4) + kq];

            #pragma unroll 4
            for (int rr = 0; rr < 16; ++rr) {
                int row = (rg << 5) + (rr << 1) + rp;
                ull a0 = 0, a1 = 0, a2 = 0, a3 = 0;
                #pragma unroll
                for (int jj = 0; jj < 2; ++jj) {
                    ulonglong2 w = Wsm[((jj << 4) + kq) * WSTRIDE + row];
                    ffma2(a0, w.x, ha[0][jj].x); ffma2(a0, w.y, ha[0][jj].y);
                    ffma2(a1, w.x, ha[1][jj].x); ffma2(a1, w.y, ha[1][jj].y);
                    ffma2(a2, w.x, ha[2][jj].x); ffma2(a2, w.y, ha[2][jj].y);
                    ffma2(a3, w.x, ha[3][jj].x); ffma2(a3, w.y, ha[3][jj].y);
                }
                float s0 = pksum(a0), s1 = pksum(a1), s2 = pksum(a2), s3 = pksum(a3);
                #pragma unroll
                for (int off = 1; off < 16; off <<= 1) {
                    s0 += __shfl_xor_sync(0xffffffffu, s0, off);
                    s1 += __shfl_xor_sync(0xffffffffu, s1, off);
                    s2 += __shfl_xor_sync(0xffffffffu, s2, off);
                    s3 += __shfl_xor_sync(0xffffffffu, s3, off);
                }
                if (kq == 0) {
                    float* gp = gsm + row * GSTRIDE + (mg << 2);
                    *(float2*)(gp)     = make_float2(s0, s1);
                    *(float2*)(gp + 2) = make_float2(s2, s3);
                }
            }
        }
        __syncthreads();

        // ---- stage B: layer-1 cell update -> h1[p^1] on all 4 CTAs ----
        {
            float x = xs[p * MB + m_c];
            float g0 = gsm[(d_c)       * GSTRIDE + m_c] + fmaf(x, wih1r[0], b1r[0]);
            float g1 = gsm[(32 + d_c)  * GSTRIDE + m_c] + fmaf(x, wih1r[1], b1r[1]);
            float g2 = gsm[(64 + d_c)  * GSTRIDE + m_c] + fmaf(x, wih1r[2], b1r[2]);
            float g3 = gsm[(96 + d_c)  * GSTRIDE + m_c] + fmaf(x, wih1r[3], b1r[3]);
            float ii = sigf(g0), ff = sigf(g1), gg = tanh_fast(g2), oo = sigf(g3);
            c1 = ff * c1 + ii * gg;
            float h1n = oo * tanh_fast(c1);
            push_all(h1_u32 +
                ((((p ^ 1) * MB * 128) + (m_c << 7) + ((int)rank << 5) + d_c) << 2), h1n);
            if (tid < MB) {
                int b = bbase + tid;
                xs[(p ^ 1) * MB + tid] =
                    (b < B_DIM && t + 1 < L_DIM) ? y[b * L_DIM + t + 1] : 0.f;
            }
        }
        cluster_sync();   // h1[p^1] + h2 visible cluster-wide

        // ---- stage C: layer-2 gates over h1[p^1] and h2 ----
        {
            const ulonglong2* hb1 = (const ulonglong2*)(h1s + (p ^ 1) * MB * 128);
            const ulonglong2* hb2 = (const ulonglong2*)h2s;
            ulonglong2 ha[4][2], hc[4][2];
            #pragma unroll
            for (int m = 0; m < 4; ++m)
                #pragma unroll
                for (int jj = 0; jj < 2; ++jj) {
                    int idx = ((mg << 2) + m) * 32 + (jj << 4) + kq;
                    ha[m][jj] = hb1[idx];
                    hc[m][jj] = hb2[idx];
                }

            #pragma unroll 4
            for (int rr = 0; rr < 16; ++rr) {
                int row = (rg << 5) + (rr << 1) + rp;
                ull a0 = 0, a1 = 0, a2 = 0, a3 = 0;
                #pragma unroll
                for (int jj = 0; jj < 2; ++jj) {
                    ulonglong2 wi = Wsm[(32 + (jj << 4) + kq) * WSTRIDE + row];
                    ulonglong2 wh = Wsm[(64 + (jj << 4) + kq) * WSTRIDE + row];
                    ffma2(a0, wi.x, ha[0][jj].x); ffma2(a0, wi.y, ha[0][jj].y);
                    ffma2(a0, wh.x, hc[0][jj].x); ffma2(a0, wh.y, hc[0][jj].y);
                    ffma2(a1, wi.x, ha[1][jj].x); ffma2(a1, wi.y, ha[1][jj].y);
                    ffma2(a1, wh.x, hc[1][jj].x); ffma2(a1, wh.y, hc[1][jj].y);
                    ffma2(a2, wi.x, ha[2][jj].x); ffma2(a2, wi.y, ha[2][jj].y);
                    ffma2(a2, wh.x, hc[2][jj].x); ffma2(a2, wh.y, hc[2][jj].y);
                    ffma2(a3, wi.x, ha[3][jj].x); ffma2(a3, wi.y, ha[3][jj].y);
                    ffma2(a3, wh.x, hc[3][jj].x); ffma2(a3, wh.y, hc[3][jj].y);
                }
                float s0 = pksum(a0), s1 = pksum(a1), s2 = pksum(a2), s3 = pksum(a3);
                #pragma unroll
                for (int off = 1; off < 16; off <<= 1) {
                    s0 += __shfl_xor_sync(0xffffffffu, s0, off);
                    s1 += __shfl_xor_sync(0xffffffffu, s1, off);
                    s2 += __shfl_xor_sync(0xffffffffu, s2, off);
                    s3 += __shfl_xor_sync(0xffffffffu, s3, off);
                }
                if (kq == 0) {
                    float* gp = gsm + row * GSTRIDE + (mg << 2);
                    *(float2*)(gp)     = make_float2(s0, s1);
                    *(float2*)(gp + 2) = make_float2(s2, s3);
                }
            }
        }
        __syncthreads();

        // ---- stage D: layer-2 cell update + output partial ----
        {
            float g0 = gsm[(d_c)      * GSTRIDE + m_c] + b2r[0];
            float g1 = gsm[(32 + d_c) * GSTRIDE + m_c] + b2r[1];
            float g2 = gsm[(64 + d_c) * GSTRIDE + m_c] + b2r[2];
            float g3 = gsm[(96 + d_c) * GSTRIDE + m_c] + b2r[3];
            float ii = sigf(g0), ff = sigf(g1), gg = tanh_fast(g2), oo = sigf(g3);
            c2 = ff * c2 + ii * gg;
            h2n = oo * tanh_fast(c2);       // published at next step's phase 0
            float op = h2n * wlin_d;
            #pragma unroll
            for (int off = 16; off > 0; off >>= 1)
                op += __shfl_xor_sync(0xffffffffu, op, off);
            if (d_c == 0)
                push_rank0(op_u32 + ((((int)rank) * MB + m_c) << 2), op);
        }
        cluster_sync();   // outp visible on rank 0; buffers safe to rotate

        // ---- stage E: rank-0 writes scalar outputs ----
        if (rank == 0 && tid < MB) {
            int b = bbase + tid;
            if (b < B_DIM)
                out[b * L_DIM + t] = outp[tid] + outp[MB + tid] +
                                     outp[2 * MB + tid] + outp[3 * MB + tid] + blin0;
        }
        p ^= 1;
    }
}

extern "C" void kernel_launch(void* const* d_in, const int* in_sizes, int n_in,
                              void* d_out, int out_size) {
    const float* y    = (const float*)d_in[0];
    const float* Wih1 = (const float*)d_in[1];
    const float* Whh1 = (const float*)d_in[2];
    const float* bih1 = (const float*)d_in[3];
    const float* bhh1 = (const float*)d_in[4];
    const float* Wih2 = (const float*)d_in[5];
    const float* Whh2 = (const float*)d_in[6];
    const float* bih2 = (const float*)d_in[7];
    const float* bhh2 = (const float*)d_in[8];
    const float* Wlin = (const float*)d_in[9];
    const float* blin = (const float*)d_in[10];
    float* out = (float*)d_out;

    cudaFuncSetAttribute(lstm_main, cudaFuncAttributeMaxDynamicSharedMemorySize,
                         SMEM_BYTES);

    pack_weights<<<(4 * 96 * 128 + 255) / 256, 256>>>(Whh1, Wih2, Whh2);
    lstm_main<<<NBLK, BLK_T, SMEM_BYTES>>>(y, Wih1, bih1, bhh1, bih2, bhh2,
                                           Wlin, blin, out);
}

// round 12
// speedup vs baseline: 2.0238x; 2.0238x over previous
#include <cuda_runtime.h>
#include <cstdint>

// LSTM_1279900254644: 2-layer LSTM, B=512, L=1000, H=128.
// Cluster-of-4 + warp-level tf32 mma.sync (HMMA; base PTX, no sm_103a gating).
// Each CTA: M=128 gate rows (own 32 dims x 4 gates) x N=16 batches x K=128.
// Weight error removed via hi/lo 2-term split; h rounded to tf32 at cell stage.
// W_hh1 fragments register-resident; W_ih2/W_hh2 fragment-packed in SMEM.

#define L_DIM  1000
#define NTHR   256         // 8 warps
#define NBLK   128         // 32 clusters x 4 CTAs, one wave

#define HSTRIDE 24         // h row stride in floats (conflict-free B-frag banks)
#define HBUF    12288u     // one h buffer: 128 * 24 * 4 bytes

// ---- SMEM byte offsets ----
#define A_OFF    0u        // packed A frags: [mat 2][warp 8][kt 16][lane 32][4f] = 131072
#define H1_OFF   131072u   // h1: 2 buffers x 12288
#define H2_OFF   155648u   // h2: 2 buffers x 12288
#define GSM_OFF  180224u   // gates: 128 rows x 18 floats = 9216
#define H2L_OFF  189440u   // output partials: 32 x 17 floats = 2176
#define XS_OFF   191616u   // x_t: 16 floats
#define OUTP_OFF 191680u   // cluster output partials: 64 floats
#define SMEM_SZ  192192

typedef unsigned long long ull;

__device__ __forceinline__ float sigf(float x) {
    return __fdividef(1.f, 1.f + __expf(-x));
}
__device__ __forceinline__ float tanh_fast(float x) {
    return 1.f - __fdividef(2.f, __expf(2.f * x) + 1.f);
}
__device__ __forceinline__ uint32_t smem_u32(const void* p) {
    uint32_t a;
    asm("{ .reg .u64 t; cvta.to.shared.u64 t, %1; cvt.u32.u64 %0, t; }" : "=r"(a) : "l"(p));
    return a;
}
__device__ __forceinline__ void cluster_sync() {
    asm volatile("barrier.cluster.arrive.aligned;" ::: "memory");
    asm volatile("barrier.cluster.wait.aligned;" ::: "memory");
}
__device__ __forceinline__ void push_all(uint32_t laddr, float v) {
    #pragma unroll
    for (int r = 0; r < 4; ++r) {
        uint32_t ra;
        asm volatile("mapa.shared::cluster.u32 %0, %1, %2;" : "=r"(ra) : "r"(laddr), "r"(r));
        asm volatile("st.shared::cluster.f32 [%0], %1;" :: "r"(ra), "f"(v) : "memory");
    }
}
__device__ __forceinline__ void push_rank0(uint32_t laddr, float v) {
    uint32_t ra;
    asm volatile("mapa.shared::cluster.u32 %0, %1, %2;" : "=r"(ra) : "r"(laddr), "r"(0));
    asm volatile("st.shared::cluster.f32 [%0], %1;" :: "r"(ra), "f"(v) : "memory");
}
// round-to-nearest fp32 -> tf32 (result is fp32 bits with low 13 mantissa bits 0)
__device__ __forceinline__ float rnd_tf32(float f) {
    uint32_t u;
    asm("cvt.rna.tf32.f32 %0, %1;" : "=r"(u) : "f"(f));
    return __uint_as_float(u);
}
__device__ __forceinline__ void mma_tf32(float* d, const uint32_t* a,
                                         uint32_t b0, uint32_t b1) {
    asm volatile(
        "mma.sync.aligned.m16n8k8.row.col.f32.tf32.tf32.f32 "
        "{%0,%1,%2,%3}, {%4,%5,%6,%7}, {%8,%9}, {%0,%1,%2,%3};"
        : "+f"(d[0]), "+f"(d[1]), "+f"(d[2]), "+f"(d[3])
        : "r"(a[0]), "r"(a[1]), "r"(a[2]), "r"(a[3]), "r"(b0), "r"(b1));
}
// split fp32 -> (hi tf32-exact, lo remainder) as b32 operands
__device__ __forceinline__ void split4(const float* a, uint32_t* hi, uint32_t* lo) {
    #pragma unroll
    for (int s = 0; s < 4; ++s) {
        float h = rnd_tf32(a[s]);
        hi[s] = __float_as_uint(h);
        lo[s] = __float_as_uint(a[s] - h);
    }
}

__global__ __launch_bounds__(NTHR, 1) __cluster_dims__(4, 1, 1)
void lstm_mma(const float* __restrict__ y,
              const float* __restrict__ Wih1,
              const float* __restrict__ Whh1,
              const float* __restrict__ bih1,
              const float* __restrict__ bhh1,
              const float* __restrict__ Wih2,
              const float* __restrict__ Whh2,
              const float* __restrict__ bih2,
              const float* __restrict__ bhh2,
              const float* __restrict__ Wlin,
              const float* __restrict__ blin,
              float* __restrict__ out) {
    extern __shared__ unsigned char sm[];
    const int tid  = threadIdx.x;
    const int lane = tid & 31;
    const int w    = tid >> 5;
    uint32_t rank;
    asm("mov.u32 %0, %%cluster_ctarank;" : "=r"(rank));
    const int q     = (int)rank;
    const int bbase = (blockIdx.x >> 2) * 16;
    const uint32_t smb = smem_u32(sm);

    float* gsm  = (float*)(sm + GSM_OFF);
    float* h2l  = (float*)(sm + H2L_OFF);
    float* xs   = (float*)(sm + XS_OFF);
    float* outp = (float*)(sm + OUTP_OFF);

    // ---- fragment index helpers (mma.m16n8k8 A-fragment thread mapping) ----
    // slot s: row = 16*w + lane/4 + 8*(s&1), col = 8*kt + lane%4 + 4*(s>>1)
    // local row lrow -> gate = lrow>>5, dim = lrow&31; weight row = gate*128 + q*32 + dim

    // ---- init: W_hh1 fragments -> registers; W_ih2/W_hh2 fragments -> SMEM ----
    float a1r[16][4];
    #pragma unroll
    for (int kt = 0; kt < 16; ++kt)
        #pragma unroll
        for (int s = 0; s < 4; ++s) {
            int lrow = 16 * w + (lane >> 2) + 8 * (s & 1);
            int col  = 8 * kt + (lane & 3) + 4 * (s >> 1);
            int grow = ((lrow >> 5) << 7) + (q << 5) + (lrow & 31);
            a1r[kt][s] = Whh1[grow * 128 + col];
        }
    for (int mat = 0; mat < 2; ++mat) {
        const float* src = (mat == 0) ? Wih2 : Whh2;
        #pragma unroll
        for (int kt = 0; kt < 16; ++kt) {
            float4 v;
            float* vp = (float*)&v;
            #pragma unroll
            for (int s = 0; s < 4; ++s) {
                int lrow = 16 * w + (lane >> 2) + 8 * (s & 1);
                int col  = 8 * kt + (lane & 3) + 4 * (s >> 1);
                int grow = ((lrow >> 5) << 7) + (q << 5) + (lrow & 31);
                vp[s] = src[grow * 128 + col];
            }
            *(float4*)(sm + A_OFF + (((mat * 8 + w) * 16 + kt) << 9) + lane * 16) = v;
        }
    }
    // zero all h buffers
    for (int i = tid; i < (int)(4 * HBUF / 16); i += NTHR)
        ((float4*)(sm + H1_OFF))[i] = make_float4(0.f, 0.f, 0.f, 0.f);

    // cell-stage constants: this thread owns dim d (local), batches m0, m0+1
    const int d  = tid >> 3;
    const int m0 = (tid & 7) << 1;
    const int dg = (q << 5) + d;            // global dim
    float wx[4], bb1[4], bb2[4];
    #pragma unroll
    for (int g = 0; g < 4; ++g) {
        int gr = (g << 7) + dg;
        wx[g]  = Wih1[gr];
        bb1[g] = bih1[gr] + bhh1[gr];
        bb2[g] = bih2[gr] + bhh2[gr];
    }
    const float wlin_d = Wlin[dg];
    const float blin0  = blin[0];

    __syncthreads();
    cluster_sync();

    float c1a = 0.f, c1b = 0.f, c2a = 0.f, c2b = 0.f;
    int p = 0;

    for (int t = 0; t < L_DIM; ++t) {
        // ---- stage A: GEMM1 = Whh1 @ h1[p]  (2-term hi/lo) ----
        {
            const float* h1p = (const float*)(sm + H1_OFF + p * HBUF);
            float acc0[4] = {0.f, 0.f, 0.f, 0.f};
            float acc1[4] = {0.f, 0.f, 0.f, 0.f};
            #pragma unroll
            for (int kt = 0; kt < 16; ++kt) {
                const float* hb = h1p + (8 * kt + (lane & 3)) * HSTRIDE + (lane >> 2);
                uint32_t b00 = __float_as_uint(hb[0]);
                uint32_t b01 = __float_as_uint(hb[4 * HSTRIDE]);
                uint32_t b10 = __float_as_uint(hb[8]);
                uint32_t b11 = __float_as_uint(hb[4 * HSTRIDE + 8]);
                uint32_t hi[4], lo[4];
                split4(a1r[kt], hi, lo);
                mma_tf32(acc0, hi, b00, b01);
                mma_tf32(acc0, lo, b00, b01);
                mma_tf32(acc1, hi, b10, b11);
                mma_tf32(acc1, lo, b10, b11);
            }
            int r0 = 16 * w + (lane >> 2);
            int cc = 2 * (lane & 3);
            *(float2*)(gsm + r0 * 18 + cc)           = make_float2(acc0[0], acc0[1]);
            *(float2*)(gsm + (r0 + 8) * 18 + cc)     = make_float2(acc0[2], acc0[3]);
            *(float2*)(gsm + r0 * 18 + cc + 8)       = make_float2(acc1[0], acc1[1]);
            *(float2*)(gsm + (r0 + 8) * 18 + cc + 8) = make_float2(acc1[2], acc1[3]);
        }
        if (tid < 16) xs[tid] = y[(bbase + tid) * L_DIM + t];
        __syncthreads();

        // ---- stage B: cell 1 -> h1[p^1] pushed to all 4 CTAs ----
        {
            float xa = xs[m0], xb = xs[m0 + 1];
            float ga[4], gb[4];
            #pragma unroll
            for (int g = 0; g < 4; ++g) {
                float2 v = *(const float2*)(gsm + ((g << 5) + d) * 18 + m0);
                ga[g] = v.x; gb[g] = v.y;
            }
            float Ia = sigf(ga[0] + fmaf(xa, wx[0], bb1[0]));
            float Fa = sigf(ga[1] + fmaf(xa, wx[1], bb1[1]));
            float Ga = tanh_fast(ga[2] + fmaf(xa, wx[2], bb1[2]));
            float Oa = sigf(ga[3] + fmaf(xa, wx[3], bb1[3]));
            c1a = Fa * c1a + Ia * Ga;
            float h1na = Oa * tanh_fast(c1a);
            float Ib = sigf(gb[0] + fmaf(xb, wx[0], bb1[0]));
            float Fb = sigf(gb[1] + fmaf(xb, wx[1], bb1[1]));
            float Gb = tanh_fast(gb[2] + fmaf(xb, wx[2], bb1[2]));
            float Ob = sigf(gb[3] + fmaf(xb, wx[3], bb1[3]));
            c1b = Fb * c1b + Ib * Gb;
            float h1nb = Ob * tanh_fast(c1b);
            uint32_t base = smb + H1_OFF + (p ^ 1) * HBUF + ((dg * HSTRIDE + m0) << 2);
            push_all(base,     rnd_tf32(h1na));
            push_all(base + 4, rnd_tf32(h1nb));
        }
        cluster_sync();   // h1[p^1] visible cluster-wide; gsm reads done

        // ---- stage C: GEMM2 = Wih2 @ h1[p^1] + Whh2 @ h2[p]  (2-term each) ----
        {
            const float* h1n = (const float*)(sm + H1_OFF + (p ^ 1) * HBUF);
            const float* h2p = (const float*)(sm + H2_OFF + p * HBUF);
            float acc0[4] = {0.f, 0.f, 0.f, 0.f};
            float acc1[4] = {0.f, 0.f, 0.f, 0.f};
            #pragma unroll
            for (int kt = 0; kt < 16; ++kt) {
                int koff = (8 * kt + (lane & 3)) * HSTRIDE + (lane >> 2);
                const float* hb1 = h1n + koff;
                const float* hb2 = h2p + koff;
                uint32_t p00 = __float_as_uint(hb1[0]);
                uint32_t p01 = __float_as_uint(hb1[4 * HSTRIDE]);
                uint32_t p10 = __float_as_uint(hb1[8]);
                uint32_t p11 = __float_as_uint(hb1[4 * HSTRIDE + 8]);
                uint32_t q00 = __float_as_uint(hb2[0]);
                uint32_t q01 = __float_as_uint(hb2[4 * HSTRIDE]);
                uint32_t q10 = __float_as_uint(hb2[8]);
                uint32_t q11 = __float_as_uint(hb2[4 * HSTRIDE + 8]);
                float4 a2 = *(const float4*)(sm + A_OFF + ((w * 16 + kt) << 9) + lane * 16);
                float4 a3 = *(const float4*)(sm + A_OFF + (((8 + w) * 16 + kt) << 9) + lane * 16);
                uint32_t hi[4], lo[4];
                split4((const float*)&a2, hi, lo);
                mma_tf32(acc0, hi, p00, p01);
                mma_tf32(acc0, lo, p00, p01);
                mma_tf32(acc1, hi, p10, p11);
                mma_tf32(acc1, lo, p10, p11);
                split4((const float*)&a3, hi, lo);
                mma_tf32(acc0, hi, q00, q01);
                mma_tf32(acc0, lo, q00, q01);
                mma_tf32(acc1, hi, q10, q11);
                mma_tf32(acc1, lo, q10, q11);
            }
            int r0 = 16 * w + (lane >> 2);
            int cc = 2 * (lane & 3);
            *(float2*)(gsm + r0 * 18 + cc)           = make_float2(acc0[0], acc0[1]);
            *(float2*)(gsm + (r0 + 8) * 18 + cc)     = make_float2(acc0[2], acc0[3]);
            *(float2*)(gsm + r0 * 18 + cc + 8)       = make_float2(acc1[0], acc1[1]);
            *(float2*)(gsm + (r0 + 8) * 18 + cc + 8) = make_float2(acc1[2], acc1[3]);
        }
        __syncthreads();

        // ---- stage D: cell 2 -> h2[p^1]; output partials ----
        {
            float ga[4], gb[4];
            #pragma unroll
            for (int g = 0; g < 4; ++g) {
                float2 v = *(const float2*)(gsm + ((g << 5) + d) * 18 + m0);
                ga[g] = v.x; gb[g] = v.y;
            }
            float Ia = sigf(ga[0] + bb2[0]);
            float Fa = sigf(ga[1] + bb2[1]);
            float Ga = tanh_fast(ga[2] + bb2[2]);
            float Oa = sigf(ga[3] + bb2[3]);
            c2a = Fa * c2a + Ia * Ga;
            float h2na = Oa * tanh_fast(c2a);
            float Ib = sigf(gb[0] + bb2[0]);
            float Fb = sigf(gb[1] + bb2[1]);
            float Gb = tanh_fast(gb[2] + bb2[2]);
            float Ob = sigf(gb[3] + bb2[3]);
            c2b = Fb * c2b + Ib * Gb;
            float h2nb = Ob * tanh_fast(c2b);
            uint32_t base = smb + H2_OFF + (p ^ 1) * HBUF + ((dg * HSTRIDE + m0) << 2);
            push_all(base,     rnd_tf32(h2na));
            push_all(base + 4, rnd_tf32(h2nb));
            h2l[d * 17 + m0]     = h2na * wlin_d;
            h2l[d * 17 + m0 + 1] = h2nb * wlin_d;
        }
        __syncthreads();
        if (tid < 16) {
            float s = 0.f;
            #pragma unroll 8
            for (int dd = 0; dd < 32; ++dd) s += h2l[dd * 17 + tid];
            push_rank0(smb + OUTP_OFF + (((q << 4) + tid) << 2), s);
        }
        cluster_sync();   // h2[p^1] + outp visible

        if (q == 0 && tid < 16) {
            out[(bbase + tid) * L_DIM + t] =
                outp[tid] + outp[16 + tid] + outp[32 + tid] + outp[48 + tid] + blin0;
        }
        p ^= 1;
    }
}

extern "C" void kernel_launch(void* const* d_in, const int* in_sizes, int n_in,
                              void* d_out, int out_size) {
    const float* y    = (const float*)d_in[0];
    const float* Wih1 = (const float*)d_in[1];
    const float* Whh1 = (const float*)d_in[2];
    const float* bih1 = (const float*)d_in[3];
    const float* bhh1 = (const float*)d_in[4];
    const float* Wih2 = (const float*)d_in[5];
    const float* Whh2 = (const float*)d_in[6];
    const float* bih2 = (const float*)d_in[7];
    const float* bhh2 = (const float*)d_in[8];
    const float* Wlin = (const float*)d_in[9];
    const float* blin = (const float*)d_in[10];
    float* out = (float*)d_out;

    cudaFuncSetAttribute(lstm_mma, cudaFuncAttributeMaxDynamicSharedMemorySize,
                         SMEM_SZ);

    lstm_mma<<<NBLK, NTHR, SMEM_SZ>>>(y, Wih1, Whh1, bih1, bhh1,
                                      Wih2, Whh2, bih2, bhh2,
                                      Wlin, blin, out);
}

// round 13
// speedup vs baseline: 3.0725x; 1.5181x over previous
#include <cuda_runtime.h>
#include <cstdint>

// LSTM_1279900254644: 2-layer LSTM, B=512, L=1000, H=128.
// Cluster-of-4 + warp-level tf32 mma.sync. Round 12 -> 13 changes:
//  - single-term tf32 weights, pre-rounded at init (no per-step split4)
//  - one cluster_sync/step (deferred output write, double-buffered partials)
//  - shuffle-based output reduction (no h2l SMEM round trip)

#define L_DIM  1000
#define NTHR   256         // 8 warps
#define NBLK   128         // 32 clusters x 4 CTAs, one wave

#define HSTRIDE 24         // h row stride in floats (conflict-free B-frag banks)
#define HBUF    12288u     // one h buffer: 128 * 24 * 4 bytes

// ---- SMEM byte offsets ----
#define A_OFF    0u        // packed A frags (Wih2,Whh2): [mat2][w8][kt16][lane32][4f]
#define H1_OFF   131072u   // h1: 2 buffers x 12288
#define H2_OFF   155648u   // h2: 2 buffers x 12288
#define GSM_OFF  180224u   // gates: 128 rows x 18 floats = 9216
#define XS_OFF   189440u   // x_t: 16 floats
#define OUTP_OFF 189504u   // output partials: 2 bufs x 32 rw x 16 m = 4096
#define SMEM_SZ  193600

__device__ __forceinline__ float sigf(float x) {
    return __fdividef(1.f, 1.f + __expf(-x));
}
__device__ __forceinline__ float tanh_fast(float x) {
    return 1.f - __fdividef(2.f, __expf(2.f * x) + 1.f);
}
__device__ __forceinline__ uint32_t smem_u32(const void* p) {
    uint32_t a;
    asm("{ .reg .u64 t; cvta.to.shared.u64 t, %1; cvt.u32.u64 %0, t; }" : "=r"(a) : "l"(p));
    return a;
}
__device__ __forceinline__ void cluster_sync() {
    asm volatile("barrier.cluster.arrive.aligned;" ::: "memory");
    asm volatile("barrier.cluster.wait.aligned;" ::: "memory");
}
__device__ __forceinline__ void push_all(uint32_t laddr, float v) {
    #pragma unroll
    for (int r = 0; r < 4; ++r) {
        uint32_t ra;
        asm volatile("mapa.shared::cluster.u32 %0, %1, %2;" : "=r"(ra) : "r"(laddr), "r"(r));
        asm volatile("st.shared::cluster.f32 [%0], %1;" :: "r"(ra), "f"(v) : "memory");
    }
}
__device__ __forceinline__ void push_rank0(uint32_t laddr, float v) {
    uint32_t ra;
    asm volatile("mapa.shared::cluster.u32 %0, %1, %2;" : "=r"(ra) : "r"(laddr), "r"(0));
    asm volatile("st.shared::cluster.f32 [%0], %1;" :: "r"(ra), "f"(v) : "memory");
}
// round-to-nearest fp32 -> tf32 bits
__device__ __forceinline__ uint32_t rnd_tf32_u(float f) {
    uint32_t u;
    asm("cvt.rna.tf32.f32 %0, %1;" : "=r"(u) : "f"(f));
    return u;
}
__device__ __forceinline__ float rnd_tf32(float f) {
    return __uint_as_float(rnd_tf32_u(f));
}
__device__ __forceinline__ void mma_tf32(float* d, const uint32_t* a,
                                         uint32_t b0, uint32_t b1) {
    asm volatile(
        "mma.sync.aligned.m16n8k8.row.col.f32.tf32.tf32.f32 "
        "{%0,%1,%2,%3}, {%4,%5,%6,%7}, {%8,%9}, {%0,%1,%2,%3};"
        : "+f"(d[0]), "+f"(d[1]), "+f"(d[2]), "+f"(d[3])
        : "r"(a[0]), "r"(a[1]), "r"(a[2]), "r"(a[3]), "r"(b0), "r"(b1));
}

__global__ __launch_bounds__(NTHR, 1) __cluster_dims__(4, 1, 1)
void lstm_mma(const float* __restrict__ y,
              const float* __restrict__ Wih1,
              const float* __restrict__ Whh1,
              const float* __restrict__ bih1,
              const float* __restrict__ bhh1,
              const float* __restrict__ Wih2,
              const float* __restrict__ Whh2,
              const float* __restrict__ bih2,
              const float* __restrict__ bhh2,
              const float* __restrict__ Wlin,
              const float* __restrict__ blin,
              float* __restrict__ out) {
    extern __shared__ unsigned char sm[];
    const int tid  = threadIdx.x;
    const int lane = tid & 31;
    const int w    = tid >> 5;
    uint32_t rank;
    asm("mov.u32 %0, %%cluster_ctarank;" : "=r"(rank));
    const int q     = (int)rank;
    const int bbase = (blockIdx.x >> 2) * 16;
    const uint32_t smb = smem_u32(sm);

    float* gsm  = (float*)(sm + GSM_OFF);
    float* xs   = (float*)(sm + XS_OFF);
    float* outp = (float*)(sm + OUTP_OFF);

    // ---- init: W_hh1 frags (pre-rounded tf32) -> registers ----
    // slot s: row = 16*w + lane/4 + 8*(s&1), col = 8*kt + lane%4 + 4*(s>>1)
    // local row lrow -> gate = lrow>>5, dim = lrow&31; global row = gate*128 + q*32 + dim
    uint32_t a1u[16][4];
    #pragma unroll
    for (int kt = 0; kt < 16; ++kt)
        #pragma unroll
        for (int s = 0; s < 4; ++s) {
            int lrow = 16 * w + (lane >> 2) + 8 * (s & 1);
            int col  = 8 * kt + (lane & 3) + 4 * (s >> 1);
            int grow = ((lrow >> 5) << 7) + (q << 5) + (lrow & 31);
            a1u[kt][s] = rnd_tf32_u(Whh1[grow * 128 + col]);
        }
    // Wih2 / Whh2 frags (pre-rounded) -> SMEM
    for (int mat = 0; mat < 2; ++mat) {
        const float* src = (mat == 0) ? Wih2 : Whh2;
        #pragma unroll
        for (int kt = 0; kt < 16; ++kt) {
            uint32_t v[4];
            #pragma unroll
            for (int s = 0; s < 4; ++s) {
                int lrow = 16 * w + (lane >> 2) + 8 * (s & 1);
                int col  = 8 * kt + (lane & 3) + 4 * (s >> 1);
                int grow = ((lrow >> 5) << 7) + (q << 5) + (lrow & 31);
                v[s] = rnd_tf32_u(src[grow * 128 + col]);
            }
            *(uint4*)(sm + A_OFF + (((mat * 8 + w) * 16 + kt) << 9) + lane * 16) =
                make_uint4(v[0], v[1], v[2], v[3]);
        }
    }
    // zero all h buffers
    for (int i = tid; i < (int)(4 * HBUF / 16); i += NTHR)
        ((float4*)(sm + H1_OFF))[i] = make_float4(0.f, 0.f, 0.f, 0.f);

    // cell-stage roles: dim d (local), batches m0, m0+1
    const int d  = tid >> 3;
    const int m0 = (tid & 7) << 1;
    const int dg = (q << 5) + d;
    float wx[4], bb1[4], bb2[4];
    #pragma unroll
    for (int g = 0; g < 4; ++g) {
        int gr = (g << 7) + dg;
        wx[g]  = Wih1[gr];
        bb1[g] = bih1[gr] + bhh1[gr];
        bb2[g] = bih2[gr] + bhh2[gr];
    }
    const float wlin_d = Wlin[dg];
    const float blin0  = blin[0];

    __syncthreads();
    cluster_sync();

    float c1a = 0.f, c1b = 0.f, c2a = 0.f, c2b = 0.f;
    int p = 0;

    for (int t = 0; t < L_DIM; ++t) {
        // ---- stage A: GEMM1 = Whh1 @ h1[p]  (weights in regs) ----
        {
            const float* h1p = (const float*)(sm + H1_OFF + p * HBUF);
            float acc0[4] = {0.f, 0.f, 0.f, 0.f};
            float acc1[4] = {0.f, 0.f, 0.f, 0.f};
            #pragma unroll
            for (int kt = 0; kt < 16; ++kt) {
                const float* hb = h1p + (8 * kt + (lane & 3)) * HSTRIDE + (lane >> 2);
                uint32_t b00 = __float_as_uint(hb[0]);
                uint32_t b01 = __float_as_uint(hb[4 * HSTRIDE]);
                uint32_t b10 = __float_as_uint(hb[8]);
                uint32_t b11 = __float_as_uint(hb[4 * HSTRIDE + 8]);
                mma_tf32(acc0, a1u[kt], b00, b01);
                mma_tf32(acc1, a1u[kt], b10, b11);
            }
            int r0 = 16 * w + (lane >> 2);
            int cc = 2 * (lane & 3);
            *(float2*)(gsm + r0 * 18 + cc)           = make_float2(acc0[0], acc0[1]);
            *(float2*)(gsm + (r0 + 8) * 18 + cc)     = make_float2(acc0[2], acc0[3]);
            *(float2*)(gsm + r0 * 18 + cc + 8)       = make_float2(acc1[0], acc1[1]);
            *(float2*)(gsm + (r0 + 8) * 18 + cc + 8) = make_float2(acc1[2], acc1[3]);
        }
        if (tid < 16) xs[tid] = y[(bbase + tid) * L_DIM + t];
        __syncthreads();

        // ---- stage B: cell 1 -> h1[p^1] pushed to all 4 CTAs ----
        {
            float xa = xs[m0], xb = xs[m0 + 1];
            float ga[4], gb[4];
            #pragma unroll
            for (int g = 0; g < 4; ++g) {
                float2 v = *(const float2*)(gsm + ((g << 5) + d) * 18 + m0);
                ga[g] = v.x; gb[g] = v.y;
            }
            float Ia = sigf(ga[0] + fmaf(xa, wx[0], bb1[0]));
            float Fa = sigf(ga[1] + fmaf(xa, wx[1], bb1[1]));
            float Ga = tanh_fast(ga[2] + fmaf(xa, wx[2], bb1[2]));
            float Oa = sigf(ga[3] + fmaf(xa, wx[3], bb1[3]));
            c1a = Fa * c1a + Ia * Ga;
            float h1na = Oa * tanh_fast(c1a);
            float Ib = sigf(gb[0] + fmaf(xb, wx[0], bb1[0]));
            float Fb = sigf(gb[1] + fmaf(xb, wx[1], bb1[1]));
            float Gb = tanh_fast(gb[2] + fmaf(xb, wx[2], bb1[2]));
            float Ob = sigf(gb[3] + fmaf(xb, wx[3], bb1[3]));
            c1b = Fb * c1b + Ib * Gb;
            float h1nb = Ob * tanh_fast(c1b);
            uint32_t base = smb + H1_OFF + (p ^ 1) * HBUF + ((dg * HSTRIDE + m0) << 2);
            push_all(base,     rnd_tf32(h1na));
            push_all(base + 4, rnd_tf32(h1nb));
        }
        cluster_sync();   // h1[p^1] + h2[p] + prev outp pushes visible cluster-wide

        // ---- deferred output: write out[t-1] (partials synced by the barrier) ----
        if (q == 0 && tid < 16 && t > 0) {
            const float* ob = outp + ((t - 1) & 1) * 512;
            float s = blin0;
            #pragma unroll 8
            for (int rw = 0; rw < 32; ++rw) s += ob[rw * 16 + tid];
            out[(bbase + tid) * L_DIM + (t - 1)] = s;
        }

        // ---- stage C: GEMM2 = Wih2 @ h1[p^1] + Whh2 @ h2[p] ----
        {
            const float* h1n = (const float*)(sm + H1_OFF + (p ^ 1) * HBUF);
            const float* h2p = (const float*)(sm + H2_OFF + p * HBUF);
            float acc0[4] = {0.f, 0.f, 0.f, 0.f};
            float acc1[4] = {0.f, 0.f, 0.f, 0.f};
            #pragma unroll
            for (int kt = 0; kt < 16; ++kt) {
                int koff = (8 * kt + (lane & 3)) * HSTRIDE + (lane >> 2);
                const float* hb1 = h1n + koff;
                const float* hb2 = h2p + koff;
                uint32_t p00 = __float_as_uint(hb1[0]);
                uint32_t p01 = __float_as_uint(hb1[4 * HSTRIDE]);
                uint32_t p10 = __float_as_uint(hb1[8]);
                uint32_t p11 = __float_as_uint(hb1[4 * HSTRIDE + 8]);
                uint32_t q00 = __float_as_uint(hb2[0]);
                uint32_t q01 = __float_as_uint(hb2[4 * HSTRIDE]);
                uint32_t q10 = __float_as_uint(hb2[8]);
                uint32_t q11 = __float_as_uint(hb2[4 * HSTRIDE + 8]);
                uint4 a2 = *(const uint4*)(sm + A_OFF + ((w * 16 + kt) << 9) + lane * 16);
                uint4 a3 = *(const uint4*)(sm + A_OFF + (((8 + w) * 16 + kt) << 9) + lane * 16);
                mma_tf32(acc0, (const uint32_t*)&a2, p00, p01);
                mma_tf32(acc1, (const uint32_t*)&a2, p10, p11);
                mma_tf32(acc0, (const uint32_t*)&a3, q00, q01);
                mma_tf32(acc1, (const uint32_t*)&a3, q10, q11);
            }
            int r0 = 16 * w + (lane >> 2);
            int cc = 2 * (lane & 3);
            *(float2*)(gsm + r0 * 18 + cc)           = make_float2(acc0[0], acc0[1]);
            *(float2*)(gsm + (r0 + 8) * 18 + cc)     = make_float2(acc0[2], acc0[3]);
            *(float2*)(gsm + r0 * 18 + cc + 8)       = make_float2(acc1[0], acc1[1]);
            *(float2*)(gsm + (r0 + 8) * 18 + cc + 8) = make_float2(acc1[2], acc1[3]);
        }
        __syncthreads();

        // ---- stage D: cell 2 -> h2[p^1]; warp-reduced output partials ----
        {
            float ga[4], gb[4];
            #pragma unroll
            for (int g = 0; g < 4; ++g) {
                float2 v = *(const float2*)(gsm + ((g << 5) + d) * 18 + m0);
                ga[g] = v.x; gb[g] = v.y;
            }
            float Ia = sigf(ga[0] + bb2[0]);
            float Fa = sigf(ga[1] + bb2[1]);
            float Ga = tanh_fast(ga[2] + bb2[2]);
            float Oa = sigf(ga[3] + bb2[3]);
            c2a = Fa * c2a + Ia * Ga;
            float h2na = Oa * tanh_fast(c2a);
            float Ib = sigf(gb[0] + bb2[0]);
            float Fb = sigf(gb[1] + bb2[1]);
            float Gb = tanh_fast(gb[2] + bb2[2]);
            float Ob = sigf(gb[3] + bb2[3]);
            c2b = Fb * c2b + Ib * Gb;
            float h2nb = Ob * tanh_fast(c2b);
            uint32_t base = smb + H2_OFF + (p ^ 1) * HBUF + ((dg * HSTRIDE + m0) << 2);
            push_all(base,     rnd_tf32(h2na));
            push_all(base + 4, rnd_tf32(h2nb));

            // warp-local reduce over this warp's 4 dims (lane stride 8)
            float opa = h2na * wlin_d;
            float opb = h2nb * wlin_d;
            opa += __shfl_xor_sync(0xffffffffu, opa, 8);
            opa += __shfl_xor_sync(0xffffffffu, opa, 16);
            opb += __shfl_xor_sync(0xffffffffu, opb, 8);
            opb += __shfl_xor_sync(0xffffffffu, opb, 16);
            if (lane < 8) {
                // rw = q*8 + w; batches m0 = 2*lane, m0+1
                uint32_t obase = smb + OUTP_OFF +
                    (((uint32_t)(t & 1) * 512 + ((q << 3) + w) * 16 + (lane << 1)) << 2);
                push_rank0(obase,     opa);
                push_rank0(obase + 4, opb);
            }
        }
        __syncthreads();   // gsm WAR vs next stage A writes
        p ^= 1;
    }

    // ---- flush last output ----
    cluster_sync();
    if (q == 0 && tid < 16) {
        const float* ob = outp + ((L_DIM - 1) & 1) * 512;
        float s = blin0;
        #pragma unroll 8
        for (int rw = 0; rw < 32; ++rw) s += ob[rw * 16 + tid];
        out[(bbase + tid) * L_DIM + (L_DIM - 1)] = s;
    }
}

extern "C" void kernel_launch(void* const* d_in, const int* in_sizes, int n_in,
                              void* d_out, int out_size) {
    const float* y    = (const float*)d_in[0];
    const float* Wih1 = (const float*)d_in[1];
    const float* Whh1 = (const float*)d_in[2];
    const float* bih1 = (const float*)d_in[3];
    const float* bhh1 = (const float*)d_in[4];
    const float* Wih2 = (const float*)d_in[5];
    const float* Whh2 = (const float*)d_in[6];
    const float* bih2 = (const float*)d_in[7];
    const float* bhh2 = (const float*)d_in[8];
    const float* Wlin = (const float*)d_in[9];
    const float* blin = (const float*)d_in[10];
    float* out = (float*)d_out;

    cudaFuncSetAttribute(lstm_mma, cudaFuncAttributeMaxDynamicSharedMemorySize,
                         SMEM_SZ);

    lstm_mma<<<NBLK, NTHR, SMEM_SZ>>>(y, Wih1, Whh1, bih1, bhh1,
                                      Wih2, Whh2, bih2, bhh2,
                                      Wlin, blin, out);
}

// round 14
// speedup vs baseline: 4.4200x; 1.4386x over previous
#include <cuda_runtime.h>
#include <cstdint>

// LSTM_1279900254644: 2-layer LSTM, B=512, L=1000, H=128.
// Cluster-of-4 + warp tf32 mma.sync. Round 13 -> 14: fused GEMM
// (D2(t) and D1(t+1) computed together from h1new), 1 cluster_sync +
// 1 syncthreads per step, interleaved h layout (lds.64 B-frags,
// b64 packed DSMEM pushes).

#define L_DIM  1000
#define NTHR   256         // 8 warps
#define NBLK   128         // 32 clusters x 4 CTAs, one wave

#define HSTRIDE 24         // h row stride in floats
#define HBUF    12288u     // one h buffer: 128 * 24 * 4 bytes

// ---- SMEM byte offsets ----
#define A_OFF    0u        // packed A frags (Wih2,Whh2): [mat2][w8][kt16][lane32][16B]
#define H1_OFF   131072u   // h1: 2 buffers x 12288
#define H2_OFF   155648u   // h2: 2 buffers x 12288
#define GSM_OFF  180224u   // gates: 2 bufs (D2, D1next) x 128 rows x 18 floats
#define XS_OFF   198656u   // x: 2 bufs x 16 floats
#define OUTP_OFF 198784u   // output partials: 2 bufs x 32 rw x 16 slots
#define SMEM_SZ  202880

typedef unsigned long long ull;

__device__ __forceinline__ float sigf(float x) {
    return __fdividef(1.f, 1.f + __expf(-x));
}
__device__ __forceinline__ float tanh_fast(float x) {
    return 1.f - __fdividef(2.f, __expf(2.f * x) + 1.f);
}
__device__ __forceinline__ uint32_t smem_u32(const void* p) {
    uint32_t a;
    asm("{ .reg .u64 t; cvta.to.shared.u64 t, %1; cvt.u32.u64 %0, t; }" : "=r"(a) : "l"(p));
    return a;
}
__device__ __forceinline__ void cluster_sync() {
    asm volatile("barrier.cluster.arrive.aligned;" ::: "memory");
    asm volatile("barrier.cluster.wait.aligned;" ::: "memory");
}
__device__ __forceinline__ ull pack2(float a, float b) {
    ull r;
    asm("mov.b64 %0, {%1,%2};" : "=l"(r) : "f"(a), "f"(b));
    return r;
}
__device__ __forceinline__ void push_all64(uint32_t laddr, ull v) {
    #pragma unroll
    for (int r = 0; r < 4; ++r) {
        uint32_t ra;
        asm volatile("mapa.shared::cluster.u32 %0, %1, %2;" : "=r"(ra) : "r"(laddr), "r"(r));
        asm volatile("st.shared::cluster.u64 [%0], %1;" :: "r"(ra), "l"(v) : "memory");
    }
}
__device__ __forceinline__ void push_rank0_64(uint32_t laddr, ull v) {
    uint32_t ra;
    asm volatile("mapa.shared::cluster.u32 %0, %1, %2;" : "=r"(ra) : "r"(laddr), "r"(0));
    asm volatile("st.shared::cluster.u64 [%0], %1;" :: "r"(ra), "l"(v) : "memory");
}
__device__ __forceinline__ uint32_t rnd_tf32_u(float f) {
    uint32_t u;
    asm("cvt.rna.tf32.f32 %0, %1;" : "=r"(u) : "f"(f));
    return u;
}
__device__ __forceinline__ float rnd_tf32(float f) {
    return __uint_as_float(rnd_tf32_u(f));
}
__device__ __forceinline__ void mma_tf32(float* d, const uint32_t* a,
                                         uint32_t b0, uint32_t b1) {
    asm volatile(
        "mma.sync.aligned.m16n8k8.row.col.f32.tf32.tf32.f32 "
        "{%0,%1,%2,%3}, {%4,%5,%6,%7}, {%8,%9}, {%0,%1,%2,%3};"
        : "+f"(d[0]), "+f"(d[1]), "+f"(d[2]), "+f"(d[3])
        : "r"(a[0]), "r"(a[1]), "r"(a[2]), "r"(a[3]), "r"(b0), "r"(b1));
}

__global__ __launch_bounds__(NTHR, 1) __cluster_dims__(4, 1, 1)
void lstm_mma(const float* __restrict__ y,
              const float* __restrict__ Wih1,
              const float* __restrict__ Whh1,
              const float* __restrict__ bih1,
              const float* __restrict__ bhh1,
              const float* __restrict__ Wih2,
              const float* __restrict__ Whh2,
              const float* __restrict__ bih2,
              const float* __restrict__ bhh2,
              const float* __restrict__ Wlin,
              const float* __restrict__ blin,
              float* __restrict__ out) {
    extern __shared__ unsigned char sm[];
    const int tid  = threadIdx.x;
    const int lane = tid & 31;
    const int w    = tid >> 5;
    uint32_t rank;
    asm("mov.u32 %0, %%cluster_ctarank;" : "=r"(rank));
    const int q     = (int)rank;
    const int bbase = (blockIdx.x >> 2) * 16;
    const uint32_t smb = smem_u32(sm);

    float* gsm2 = (float*)(sm + GSM_OFF);                 // D2 (layer-2 gates)
    float* gsm1 = gsm2 + 128 * 18;                        // D1 (layer-1 gates, next step)
    float* xs   = (float*)(sm + XS_OFF);                  // [2][16]
    float* outp = (float*)(sm + OUTP_OFF);                // [2][32][16] (slot-interleaved)

    // ---- init: W_hh1 frags (tf32) -> registers ----
    // slot s: row = 16*w + lane/4 + 8*(s&1), col = 8*kt + lane%4 + 4*(s>>1)
    // local row lrow: gate = lrow>>5, dim = lrow&31; global row = gate*128 + q*32 + dim
    uint32_t a1u[16][4];
    #pragma unroll
    for (int kt = 0; kt < 16; ++kt)
        #pragma unroll
        for (int s = 0; s < 4; ++s) {
            int lrow = 16 * w + (lane >> 2) + 8 * (s & 1);
            int col  = 8 * kt + (lane & 3) + 4 * (s >> 1);
            int grow = ((lrow >> 5) << 7) + (q << 5) + (lrow & 31);
            a1u[kt][s] = rnd_tf32_u(Whh1[grow * 128 + col]);
        }
    // Wih2 / Whh2 frags (tf32) -> SMEM
    for (int mat = 0; mat < 2; ++mat) {
        const float* src = (mat == 0) ? Wih2 : Whh2;
        #pragma unroll
        for (int kt = 0; kt < 16; ++kt) {
            uint32_t v[4];
            #pragma unroll
            for (int s = 0; s < 4; ++s) {
                int lrow = 16 * w + (lane >> 2) + 8 * (s & 1);
                int col  = 8 * kt + (lane & 3) + 4 * (s >> 1);
                int grow = ((lrow >> 5) << 7) + (q << 5) + (lrow & 31);
                v[s] = rnd_tf32_u(src[grow * 128 + col]);
            }
            *(uint4*)(sm + A_OFF + (((mat * 8 + w) * 16 + kt) << 9) + lane * 16) =
                make_uint4(v[0], v[1], v[2], v[3]);
        }
    }
    // zero h buffers + both gsm buffers (D1 must start at 0)
    for (int i = tid; i < (int)(4 * HBUF / 16); i += NTHR)
        ((float4*)(sm + H1_OFF))[i] = make_float4(0.f, 0.f, 0.f, 0.f);
    for (int i = tid; i < 2 * 128 * 18; i += NTHR) gsm2[i] = 0.f;

    // cell roles: dim d (local), batches n0 and n0+8 (slots 2n0, 2n0+1)
    const int d  = tid >> 3;
    const int n0 = tid & 7;
    const int dg = (q << 5) + d;
    float wx[4], bb1[4], bb2[4];
    #pragma unroll
    for (int g = 0; g < 4; ++g) {
        int gr = (g << 7) + dg;
        wx[g]  = Wih1[gr];
        bb1[g] = bih1[gr] + bhh1[gr];
        bb2[g] = bih2[gr] + bhh2[gr];
    }
    const float wlin_d = Wlin[dg];
    const float blin0  = blin[0];

    if (tid < 16) xs[tid] = y[(bbase + tid) * L_DIM];
    __syncthreads();
    cluster_sync();

    float c1a = 0.f, c1b = 0.f, c2a = 0.f, c2b = 0.f;
    int p = 0;

    for (int t = 0; t < L_DIM; ++t) {
        // ---- cell 1: gates1 precomputed in gsm1; h1new -> h1[p^1] all CTAs ----
        {
            const float* xb_ = xs + (t & 1) * 16;
            float xa = xb_[n0], xb = xb_[n0 + 8];
            float ga[4], gb[4];
            #pragma unroll
            for (int g = 0; g < 4; ++g) {
                const float* gr = gsm1 + ((g << 5) + d) * 18;
                ga[g] = gr[n0];
                gb[g] = gr[n0 + 8];
            }
            float Ia = sigf(ga[0] + fmaf(xa, wx[0], bb1[0]));
            float Fa = sigf(ga[1] + fmaf(xa, wx[1], bb1[1]));
            float Ga = tanh_fast(ga[2] + fmaf(xa, wx[2], bb1[2]));
            float Oa = sigf(ga[3] + fmaf(xa, wx[3], bb1[3]));
            c1a = Fa * c1a + Ia * Ga;
            float h1na = Oa * tanh_fast(c1a);
            float Ib = sigf(gb[0] + fmaf(xb, wx[0], bb1[0]));
            float Fb = sigf(gb[1] + fmaf(xb, wx[1], bb1[1]));
            float Gb = tanh_fast(gb[2] + fmaf(xb, wx[2], bb1[2]));
            float Ob = sigf(gb[3] + fmaf(xb, wx[3], bb1[3]));
            c1b = Fb * c1b + Ib * Gb;
            float h1nb = Ob * tanh_fast(c1b);
            // slots 2n0 (batch n0), 2n0+1 (batch n0+8): one b64 push
            uint32_t base = smb + H1_OFF + (p ^ 1) * HBUF +
                            ((dg * HSTRIDE + (n0 << 1)) << 2);
            push_all64(base, pack2(rnd_tf32(h1na), rnd_tf32(h1nb)));
        }
        cluster_sync();   // h1[p^1], h2[p], outp(t-1) visible cluster-wide

        // ---- combined GEMM: D2 = Wih2@h1new + Whh2@h2 ; D1next = Whh1@h1new ----
        {
            const float* h1n  = (const float*)(sm + H1_OFF + (p ^ 1) * HBUF);
            const float* h2p_ = (const float*)(sm + H2_OFF + p * HBUF);
            float d1a[4] = {0.f, 0.f, 0.f, 0.f};
            float d1b[4] = {0.f, 0.f, 0.f, 0.f};
            float d2a[4] = {0.f, 0.f, 0.f, 0.f};
            float d2b[4] = {0.f, 0.f, 0.f, 0.f};
            #pragma unroll
            for (int kt = 0; kt < 16; ++kt) {
                int koff = (8 * kt + (lane & 3)) * HSTRIDE + ((lane >> 2) << 1);
                float2 u0 = *(const float2*)(h1n + koff);               // (n, n+8) @ k
                float2 u1 = *(const float2*)(h1n + koff + 4 * HSTRIDE); // @ k+4
                float2 v0 = *(const float2*)(h2p_ + koff);
                float2 v1 = *(const float2*)(h2p_ + koff + 4 * HSTRIDE);
                uint32_t u0x = __float_as_uint(u0.x), u0y = __float_as_uint(u0.y);
                uint32_t u1x = __float_as_uint(u1.x), u1y = __float_as_uint(u1.y);
                uint32_t v0x = __float_as_uint(v0.x), v0y = __float_as_uint(v0.y);
                uint32_t v1x = __float_as_uint(v1.x), v1y = __float_as_uint(v1.y);
                uint4 a2 = *(const uint4*)(sm + A_OFF + ((w * 16 + kt) << 9) + lane * 16);
                uint4 a3 = *(const uint4*)(sm + A_OFF + (((8 + w) * 16 + kt) << 9) + lane * 16);
                mma_tf32(d1a, a1u[kt], u0x, u1x);
                mma_tf32(d1b, a1u[kt], u0y, u1y);
                mma_tf32(d2a, (const uint32_t*)&a2, u0x, u1x);
                mma_tf32(d2b, (const uint32_t*)&a2, u0y, u1y);
                mma_tf32(d2a, (const uint32_t*)&a3, v0x, v1x);
                mma_tf32(d2b, (const uint32_t*)&a3, v0y, v1y);
            }
            int r0 = 16 * w + (lane >> 2);
            int cc = 2 * (lane & 3);
            *(float2*)(gsm2 + r0 * 18 + cc)           = make_float2(d2a[0], d2a[1]);
            *(float2*)(gsm2 + (r0 + 8) * 18 + cc)     = make_float2(d2a[2], d2a[3]);
            *(float2*)(gsm2 + r0 * 18 + cc + 8)       = make_float2(d2b[0], d2b[1]);
            *(float2*)(gsm2 + (r0 + 8) * 18 + cc + 8) = make_float2(d2b[2], d2b[3]);
            *(float2*)(gsm1 + r0 * 18 + cc)           = make_float2(d1a[0], d1a[1]);
            *(float2*)(gsm1 + (r0 + 8) * 18 + cc)     = make_float2(d1a[2], d1a[3]);
            *(float2*)(gsm1 + r0 * 18 + cc + 8)       = make_float2(d1b[0], d1b[1]);
            *(float2*)(gsm1 + (r0 + 8) * 18 + cc + 8) = make_float2(d1b[2], d1b[3]);
        }
        // x prefetch for t+1 (overlapped; visible after the syncthreads)
        if (tid < 16 && t + 1 < L_DIM)
            xs[((t + 1) & 1) * 16 + tid] = y[(bbase + tid) * L_DIM + t + 1];
        // deferred output write for t-1 (partials were synced by cluster_sync above)
        if (q == 0 && tid < 16 && t > 0) {
            const float* ob = outp + ((t - 1) & 1) * 512;
            int slot = ((tid & 7) << 1) + (tid >> 3);
            float s = blin0;
            #pragma unroll 8
            for (int rw = 0; rw < 32; ++rw) s += ob[rw * 16 + slot];
            out[(bbase + tid) * L_DIM + (t - 1)] = s;
        }
        __syncthreads();

        // ---- cell 2: h2new -> h2[p^1]; warp-reduced output partials ----
        {
            float ga[4], gb[4];
            #pragma unroll
            for (int g = 0; g < 4; ++g) {
                const float* gr = gsm2 + ((g << 5) + d) * 18;
                ga[g] = gr[n0];
                gb[g] = gr[n0 + 8];
            }
            float Ia = sigf(ga[0] + bb2[0]);
            float Fa = sigf(ga[1] + bb2[1]);
            float Ga = tanh_fast(ga[2] + bb2[2]);
            float Oa = sigf(ga[3] + bb2[3]);
            c2a = Fa * c2a + Ia * Ga;
            float h2na = Oa * tanh_fast(c2a);
            float Ib = sigf(gb[0] + bb2[0]);
            float Fb = sigf(gb[1] + bb2[1]);
            float Gb = tanh_fast(gb[2] + bb2[2]);
            float Ob = sigf(gb[3] + bb2[3]);
            c2b = Fb * c2b + Ib * Gb;
            float h2nb = Ob * tanh_fast(c2b);
            uint32_t base = smb + H2_OFF + (p ^ 1) * HBUF +
                            ((dg * HSTRIDE + (n0 << 1)) << 2);
            push_all64(base, pack2(rnd_tf32(h2na), rnd_tf32(h2nb)));

            // warp-local reduce over this warp's 4 dims (lane stride 8)
            float opa = h2na * wlin_d;
            float opb = h2nb * wlin_d;
            opa += __shfl_xor_sync(0xffffffffu, opa, 8);
            opa += __shfl_xor_sync(0xffffffffu, opa, 16);
            opb += __shfl_xor_sync(0xffffffffu, opb, 8);
            opb += __shfl_xor_sync(0xffffffffu, opb, 16);
            if (lane < 8) {
                // rw = q*8 + w; slots 2*lane (batch lane), 2*lane+1 (batch lane+8)
                uint32_t obase = smb + OUTP_OFF +
                    (((uint32_t)(t & 1) * 512 + ((q << 3) + w) * 16 + (lane << 1)) << 2);
                push_rank0_64(obase, pack2(opa, opb));
            }
        }
        p ^= 1;
        // no barrier here: cell2/cell1 gsm reads vs next GEMM writes are
        // separated by the cluster_sync at the top of the next iteration.
    }

    // ---- flush last output ----
    cluster_sync();
    if (q == 0 && tid < 16) {
        const float* ob = outp + ((L_DIM - 1) & 1) * 512;
        int slot = ((tid & 7) << 1) + (tid >> 3);
        float s = blin0;
        #pragma unroll 8
        for (int rw = 0; rw < 32; ++rw) s += ob[rw * 16 + slot];
        out[(bbase + tid) * L_DIM + (L_DIM - 1)] = s;
    }
}

extern "C" void kernel_launch(void* const* d_in, const int* in_sizes, int n_in,
                              void* d_out, int out_size) {
    const float* y    = (const float*)d_in[0];
    const float* Wih1 = (const float*)d_in[1];
    const float* Whh1 = (const float*)d_in[2];
    const float* bih1 = (const float*)d_in[3];
    const float* bhh1 = (const float*)d_in[4];
    const float* Wih2 = (const float*)d_in[5];
    const float* Whh2 = (const float*)d_in[6];
    const float* bih2 = (const float*)d_in[7];
    const float* bhh2 = (const float*)d_in[8];
    const float* Wlin = (const float*)d_in[9];
    const float* blin = (const float*)d_in[10];
    float* out = (float*)d_out;

    cudaFuncSetAttribute(lstm_mma, cudaFuncAttributeMaxDynamicSharedMemorySize,
                         SMEM_SZ);

    lstm_mma<<<NBLK, NTHR, SMEM_SZ>>>(y, Wih1, Whh1, bih1, bhh1,
                                      Wih2, Whh2, bih2, bhh2,
                                      Wlin, blin, out);
}

// round 15
// speedup vs baseline: 4.5667x; 1.0332x over previous
#include <cuda_runtime.h>
#include <cstdint>

// LSTM_1279900254644: 2-layer LSTM, B=512, L=1000, H=128.
// Cluster-of-4 + warp tf32 mma.sync. Round 14 -> 15:
//  - fused cell stage: cell2(t-1) + cell1(t) in one segment (2 stages/step)
//  - tanh.approx.f32 for all gate nonlinearities (1 MUFU each)
// Loop runs L_DIM+1 iters; cell2/out trail by one step.

#define L_DIM  1000
#define NTHR   256         // 8 warps
#define NBLK   128         // 32 clusters x 4 CTAs, one wave

#define HSTRIDE 24         // h row stride in floats
#define HBUF    12288u     // one h buffer: 128 * 24 * 4 bytes

// ---- SMEM byte offsets ----
#define A_OFF    0u        // packed A frags (Wih2,Whh2): [mat2][w8][kt16][lane32][16B]
#define H1_OFF   131072u   // h1: 2 buffers x 12288
#define H2_OFF   155648u   // h2: 2 buffers x 12288
#define GSM_OFF  180224u   // gates: 2 bufs (D2, D1next) x 128 rows x 18 floats
#define XS_OFF   198656u   // x: 2 bufs x 16 floats
#define OUTP_OFF 198784u   // output partials: 2 bufs x 32 rw x 16 slots
#define SMEM_SZ  202880

typedef unsigned long long ull;

__device__ __forceinline__ float tanh_a(float x) {
    float r;
    asm("tanh.approx.f32 %0, %1;" : "=f"(r) : "f"(x));
    return r;
}
__device__ __forceinline__ float sigf(float x) {
    return fmaf(tanh_a(0.5f * x), 0.5f, 0.5f);
}
__device__ __forceinline__ uint32_t smem_u32(const void* p) {
    uint32_t a;
    asm("{ .reg .u64 t; cvta.to.shared.u64 t, %1; cvt.u32.u64 %0, t; }" : "=r"(a) : "l"(p));
    return a;
}
__device__ __forceinline__ void cluster_sync() {
    asm volatile("barrier.cluster.arrive.aligned;" ::: "memory");
    asm volatile("barrier.cluster.wait.aligned;" ::: "memory");
}
__device__ __forceinline__ ull pack2(float a, float b) {
    ull r;
    asm("mov.b64 %0, {%1,%2};" : "=l"(r) : "f"(a), "f"(b));
    return r;
}
__device__ __forceinline__ void push_all64(uint32_t laddr, ull v) {
    #pragma unroll
    for (int r = 0; r < 4; ++r) {
        uint32_t ra;
        asm volatile("mapa.shared::cluster.u32 %0, %1, %2;" : "=r"(ra) : "r"(laddr), "r"(r));
        asm volatile("st.shared::cluster.u64 [%0], %1;" :: "r"(ra), "l"(v) : "memory");
    }
}
__device__ __forceinline__ void push_rank0_64(uint32_t laddr, ull v) {
    uint32_t ra;
    asm volatile("mapa.shared::cluster.u32 %0, %1, %2;" : "=r"(ra) : "r"(laddr), "r"(0));
    asm volatile("st.shared::cluster.u64 [%0], %1;" :: "r"(ra), "l"(v) : "memory");
}
__device__ __forceinline__ uint32_t rnd_tf32_u(float f) {
    uint32_t u;
    asm("cvt.rna.tf32.f32 %0, %1;" : "=r"(u) : "f"(f));
    return u;
}
__device__ __forceinline__ float rnd_tf32(float f) {
    return __uint_as_float(rnd_tf32_u(f));
}
__device__ __forceinline__ void mma_tf32(float* d, const uint32_t* a,
                                         uint32_t b0, uint32_t b1) {
    asm volatile(
        "mma.sync.aligned.m16n8k8.row.col.f32.tf32.tf32.f32 "
        "{%0,%1,%2,%3}, {%4,%5,%6,%7}, {%8,%9}, {%0,%1,%2,%3};"
        : "+f"(d[0]), "+f"(d[1]), "+f"(d[2]), "+f"(d[3])
        : "r"(a[0]), "r"(a[1]), "r"(a[2]), "r"(a[3]), "r"(b0), "r"(b1));
}

__global__ __launch_bounds__(NTHR, 1) __cluster_dims__(4, 1, 1)
void lstm_mma(const float* __restrict__ y,
              const float* __restrict__ Wih1,
              const float* __restrict__ Whh1,
              const float* __restrict__ bih1,
              const float* __restrict__ bhh1,
              const float* __restrict__ Wih2,
              const float* __restrict__ Whh2,
              const float* __restrict__ bih2,
              const float* __restrict__ bhh2,
              const float* __restrict__ Wlin,
              const float* __restrict__ blin,
              float* __restrict__ out) {
    extern __shared__ unsigned char sm[];
    const int tid  = threadIdx.x;
    const int lane = tid & 31;
    const int w    = tid >> 5;
    uint32_t rank;
    asm("mov.u32 %0, %%cluster_ctarank;" : "=r"(rank));
    const int q     = (int)rank;
    const int bbase = (blockIdx.x >> 2) * 16;
    const uint32_t smb = smem_u32(sm);

    float* gsm2 = (float*)(sm + GSM_OFF);                 // D2(t-1) gates
    float* gsm1 = gsm2 + 128 * 18;                        // D1(t) gates
    float* xs   = (float*)(sm + XS_OFF);                  // [2][16]
    float* outp = (float*)(sm + OUTP_OFF);                // [2][32][16]

    // ---- init: W_hh1 frags (tf32) -> registers ----
    // slot s: row = 16*w + lane/4 + 8*(s&1), col = 8*kt + lane%4 + 4*(s>>1)
    // local row lrow: gate = lrow>>5, dim = lrow&31; global row = gate*128 + q*32 + dim
    uint32_t a1u[16][4];
    #pragma unroll
    for (int kt = 0; kt < 16; ++kt)
        #pragma unroll
        for (int s = 0; s < 4; ++s) {
            int lrow = 16 * w + (lane >> 2) + 8 * (s & 1);
            int col  = 8 * kt + (lane & 3) + 4 * (s >> 1);
            int grow = ((lrow >> 5) << 7) + (q << 5) + (lrow & 31);
            a1u[kt][s] = rnd_tf32_u(Whh1[grow * 128 + col]);
        }
    // Wih2 / Whh2 frags (tf32) -> SMEM
    for (int mat = 0; mat < 2; ++mat) {
        const float* src = (mat == 0) ? Wih2 : Whh2;
        #pragma unroll
        for (int kt = 0; kt < 16; ++kt) {
            uint32_t v[4];
            #pragma unroll
            for (int s = 0; s < 4; ++s) {
                int lrow = 16 * w + (lane >> 2) + 8 * (s & 1);
                int col  = 8 * kt + (lane & 3) + 4 * (s >> 1);
                int grow = ((lrow >> 5) << 7) + (q << 5) + (lrow & 31);
                v[s] = rnd_tf32_u(src[grow * 128 + col]);
            }
            *(uint4*)(sm + A_OFF + (((mat * 8 + w) * 16 + kt) << 9) + lane * 16) =
                make_uint4(v[0], v[1], v[2], v[3]);
        }
    }
    // zero h buffers (h2(-1)=0 must hold) + both gsm buffers (D1(0)=0)
    for (int i = tid; i < (int)(4 * HBUF / 16); i += NTHR)
        ((float4*)(sm + H1_OFF))[i] = make_float4(0.f, 0.f, 0.f, 0.f);
    for (int i = tid; i < 2 * 128 * 18; i += NTHR) gsm2[i] = 0.f;

    // cell roles: dim d (local), batches n0 and n0+8 (slots 2n0, 2n0+1)
    const int d  = tid >> 3;
    const int n0 = tid & 7;
    const int dg = (q << 5) + d;
    float wx[4], bb1[4], bb2[4];
    #pragma unroll
    for (int g = 0; g < 4; ++g) {
        int gr = (g << 7) + dg;
        wx[g]  = Wih1[gr];
        bb1[g] = bih1[gr] + bhh1[gr];
        bb2[g] = bih2[gr] + bhh2[gr];
    }
    const float wlin_d = Wlin[dg];
    const float blin0  = blin[0];

    if (tid < 16) xs[tid] = y[(bbase + tid) * L_DIM];
    __syncthreads();
    cluster_sync();

    float c1a = 0.f, c1b = 0.f, c2a = 0.f, c2b = 0.f;

    for (int t = 0; t <= L_DIM; ++t) {
        const int wp = t & 1;

        // ---- fused cell stage ----
        // cell2(t-1): gates in gsm2 -> h2new -> h2[wp]; output partials(t-1)
        if (t > 0) {
            float ga[4], gb[4];
            #pragma unroll
            for (int g = 0; g < 4; ++g) {
                const float* gr = gsm2 + ((g << 5) + d) * 18;
                ga[g] = gr[n0];
                gb[g] = gr[n0 + 8];
            }
            float Ia = sigf(ga[0] + bb2[0]);
            float Fa = sigf(ga[1] + bb2[1]);
            float Ga = tanh_a(ga[2] + bb2[2]);
            float Oa = sigf(ga[3] + bb2[3]);
            c2a = Fa * c2a + Ia * Ga;
            float h2na = Oa * tanh_a(c2a);
            float Ib = sigf(gb[0] + bb2[0]);
            float Fb = sigf(gb[1] + bb2[1]);
            float Gb = tanh_a(gb[2] + bb2[2]);
            float Ob = sigf(gb[3] + bb2[3]);
            c2b = Fb * c2b + Ib * Gb;
            float h2nb = Ob * tanh_a(c2b);
            uint32_t base = smb + H2_OFF + (uint32_t)wp * HBUF +
                            ((dg * HSTRIDE + (n0 << 1)) << 2);
            push_all64(base, pack2(rnd_tf32(h2na), rnd_tf32(h2nb)));

            float opa = h2na * wlin_d;
            float opb = h2nb * wlin_d;
            opa += __shfl_xor_sync(0xffffffffu, opa, 8);
            opa += __shfl_xor_sync(0xffffffffu, opa, 16);
            opb += __shfl_xor_sync(0xffffffffu, opb, 8);
            opb += __shfl_xor_sync(0xffffffffu, opb, 16);
            if (lane < 8) {
                uint32_t obase = smb + OUTP_OFF +
                    (((uint32_t)((t - 1) & 1) * 512 + ((q << 3) + w) * 16 + (lane << 1)) << 2);
                push_rank0_64(obase, pack2(opa, opb));
            }
        }
        // cell1(t): gates in gsm1 + x(t) -> h1new -> h1[wp]
        if (t < L_DIM) {
            const float* xb_ = xs + wp * 16;
            float xa = xb_[n0], xb = xb_[n0 + 8];
            float ga[4], gb[4];
            #pragma unroll
            for (int g = 0; g < 4; ++g) {
                const float* gr = gsm1 + ((g << 5) + d) * 18;
                ga[g] = gr[n0];
                gb[g] = gr[n0 + 8];
            }
            float Ia = sigf(ga[0] + fmaf(xa, wx[0], bb1[0]));
            float Fa = sigf(ga[1] + fmaf(xa, wx[1], bb1[1]));
            float Ga = tanh_a(ga[2] + fmaf(xa, wx[2], bb1[2]));
            float Oa = sigf(ga[3] + fmaf(xa, wx[3], bb1[3]));
            c1a = Fa * c1a + Ia * Ga;
            float h1na = Oa * tanh_a(c1a);
            float Ib = sigf(gb[0] + fmaf(xb, wx[0], bb1[0]));
            float Fb = sigf(gb[1] + fmaf(xb, wx[1], bb1[1]));
            float Gb = tanh_a(gb[2] + fmaf(xb, wx[2], bb1[2]));
            float Ob = sigf(gb[3] + fmaf(xb, wx[3], bb1[3]));
            c1b = Fb * c1b + Ib * Gb;
            float h1nb = Ob * tanh_a(c1b);
            uint32_t base = smb + H1_OFF + (uint32_t)wp * HBUF +
                            ((dg * HSTRIDE + (n0 << 1)) << 2);
            push_all64(base, pack2(rnd_tf32(h1na), rnd_tf32(h1nb)));
        }
        cluster_sync();   // h1[wp], h2[wp], outp(t-1) visible cluster-wide

        // ---- deferred output write for t-1 ----
        if (q == 0 && tid < 16 && t > 0) {
            const float* ob = outp + ((t - 1) & 1) * 512;
            int slot = ((tid & 7) << 1) + (tid >> 3);
            float s = blin0;
            #pragma unroll 8
            for (int rw = 0; rw < 32; ++rw) s += ob[rw * 16 + slot];
            out[(bbase + tid) * L_DIM + (t - 1)] = s;
        }
        // x prefetch for t+1
        if (tid < 16 && t + 1 < L_DIM)
            xs[((t + 1) & 1) * 16 + tid] = y[(bbase + tid) * L_DIM + t + 1];

        // ---- combined GEMM(t): D2(t) = Wih2@h1 + Whh2@h2 ; D1(t+1) = Whh1@h1 ----
        if (t < L_DIM) {
            const float* h1n  = (const float*)(sm + H1_OFF + (uint32_t)wp * HBUF);
            const float* h2p_ = (const float*)(sm + H2_OFF + (uint32_t)wp * HBUF);
            float d1a[4] = {0.f, 0.f, 0.f, 0.f};
            float d1b[4] = {0.f, 0.f, 0.f, 0.f};
            float d2a[4] = {0.f, 0.f, 0.f, 0.f};
            float d2b[4] = {0.f, 0.f, 0.f, 0.f};
            #pragma unroll
            for (int kt = 0; kt < 16; ++kt) {
                int koff = (8 * kt + (lane & 3)) * HSTRIDE + ((lane >> 2) << 1);
                float2 u0 = *(const float2*)(h1n + koff);
                float2 u1 = *(const float2*)(h1n + koff + 4 * HSTRIDE);
                float2 v0 = *(const float2*)(h2p_ + koff);
                float2 v1 = *(const float2*)(h2p_ + koff + 4 * HSTRIDE);
                uint32_t u0x = __float_as_uint(u0.x), u0y = __float_as_uint(u0.y);
                uint32_t u1x = __float_as_uint(u1.x), u1y = __float_as_uint(u1.y);
                uint32_t v0x = __float_as_uint(v0.x), v0y = __float_as_uint(v0.y);
                uint32_t v1x = __float_as_uint(v1.x), v1y = __float_as_uint(v1.y);
                uint4 a2 = *(const uint4*)(sm + A_OFF + ((w * 16 + kt) << 9) + lane * 16);
                uint4 a3 = *(const uint4*)(sm + A_OFF + (((8 + w) * 16 + kt) << 9) + lane * 16);
                mma_tf32(d1a, a1u[kt], u0x, u1x);
                mma_tf32(d1b, a1u[kt], u0y, u1y);
                mma_tf32(d2a, (const uint32_t*)&a2, u0x, u1x);
                mma_tf32(d2b, (const uint32_t*)&a2, u0y, u1y);
                mma_tf32(d2a, (const uint32_t*)&a3, v0x, v1x);
                mma_tf32(d2b, (const uint32_t*)&a3, v0y, v1y);
            }
            int r0 = 16 * w + (lane >> 2);
            int cc = 2 * (lane & 3);
            *(float2*)(gsm2 + r0 * 18 + cc)           = make_float2(d2a[0], d2a[1]);
            *(float2*)(gsm2 + (r0 + 8) * 18 + cc)     = make_float2(d2a[2], d2a[3]);
            *(float2*)(gsm2 + r0 * 18 + cc + 8)       = make_float2(d2b[0], d2b[1]);
            *(float2*)(gsm2 + (r0 + 8) * 18 + cc + 8) = make_float2(d2b[2], d2b[3]);
            *(float2*)(gsm1 + r0 * 18 + cc)           = make_float2(d1a[0], d1a[1]);
            *(float2*)(gsm1 + (r0 + 8) * 18 + cc)     = make_float2(d1a[2], d1a[3]);
            *(float2*)(gsm1 + r0 * 18 + cc + 8)       = make_float2(d1b[0], d1b[1]);
            *(float2*)(gsm1 + (r0 + 8) * 18 + cc + 8) = make_float2(d1b[2], d1b[3]);
        }
        __syncthreads();   // gsm writes visible to next fused cell
    }
}

extern "C" void kernel_launch(void* const* d_in, const int* in_sizes, int n_in,
                              void* d_out, int out_size) {
    const float* y    = (const float*)d_in[0];
    const float* Wih1 = (const float*)d_in[1];
    const float* Whh1 = (const float*)d_in[2];
    const float* bih1 = (const float*)d_in[3];
    const float* bhh1 = (const float*)d_in[4];
    const float* Wih2 = (const float*)d_in[5];
    const float* Whh2 = (const float*)d_in[6];
    const float* bih2 = (const float*)d_in[7];
    const float* bhh2 = (const float*)d_in[8];
    const float* Wlin = (const float*)d_in[9];
    const float* blin = (const float*)d_in[10];
    float* out = (float*)d_out;

    cudaFuncSetAttribute(lstm_mma, cudaFuncAttributeMaxDynamicSharedMemorySize,
                         SMEM_SZ);

    lstm_mma<<<NBLK, NTHR, SMEM_SZ>>>(y, Wih1, Whh1, bih1, bhh1,
                                      Wih2, Whh2, bih2, bhh2,
                                      Wlin, blin, out);
}